// round 1
// baseline (speedup 1.0000x reference)
#include <cuda_runtime.h>
#include <cuda_bf16.h>
#include <math.h>

// Problem constants
#define NB 2
#define EE 16
#define CC 16
#define VV (64*128*128)        // 1,048,576 voxels per batch
#define CHUNK 2048             // voxels per pass-1 block
#define P1_BLOCKS (VV / CHUNK) // 512
#define P2_BLOCKS 256

#define DELTA_VAR 0.5f
#define DELTA_DIST 1.5f

// Scratch (device globals; no allocation allowed)
__device__ float g_sums[NB][CC][EE];
__device__ float g_counts[NB][CC];
__device__ float g_var[NB][CC];

// ---------------------------------------------------------------------------
// Kernel 0: zero scratch
// ---------------------------------------------------------------------------
__global__ void init_kernel() {
    int tid = threadIdx.x;
    float* s = &g_sums[0][0][0];
    for (int i = tid; i < NB*CC*EE; i += blockDim.x) s[i] = 0.0f;
    float* c = &g_counts[0][0];
    for (int i = tid; i < NB*CC; i += blockDim.x) c[i] = 0.0f;
    float* v = &g_var[0][0];
    for (int i = tid; i < NB*CC; i += blockDim.x) v[i] = 0.0f;
}

// ---------------------------------------------------------------------------
// Kernel 1: per-cluster sums + counts.
// 512 threads = 16 warps; warp w handles embedding plane e = w.
// Each lane owns a private smem column acc[label*32 + lane] -> bank == lane,
// so accumulation is conflict-free and atomic-free.
// ---------------------------------------------------------------------------
__global__ __launch_bounds__(512, 4)
void pass1_kernel(const float* __restrict__ x, const int* __restrict__ t) {
    __shared__ int   labels[CHUNK];                    // 8 KB
    __shared__ float acc[EE * CC * 32];                // 32 KB (per-warp 16c x 32lane)
    __shared__ float cacc[CC * 32];                    // 2 KB  (counts, warp 0 only)

    const int n    = blockIdx.y;
    const int base = blockIdx.x * CHUNK;
    const int tid  = threadIdx.x;
    const int w    = tid >> 5;
    const int lane = tid & 31;

    // stage labels for this chunk (read once from GMEM)
    const int* tp = t + (size_t)n * VV + base;
    for (int i = tid; i < CHUNK; i += 512) labels[i] = __ldcs(tp + i);

    for (int i = tid; i < EE * CC * 32; i += 512) acc[i] = 0.0f;
    for (int i = tid; i < CC * 32;      i += 512) cacc[i] = 0.0f;
    __syncthreads();

    float* myacc = acc + w * (CC * 32);
    const float* xp = x + ((size_t)n * EE + w) * VV + base;

    if (w == 0) {
        // warp 0 also accumulates counts
        for (int i = lane; i < CHUNK; i += 32) {
            int   lab = labels[i];
            float v   = __ldcs(xp + i);
            myacc[lab * 32 + lane] += v;
            cacc [lab * 32 + lane] += 1.0f;
        }
    } else {
        for (int i = lane; i < CHUNK; i += 32) {
            int   lab = labels[i];
            float v   = __ldcs(xp + i);
            myacc[lab * 32 + lane] += v;
        }
    }

    // per-warp reduction of the 16 cluster columns, then one atomic each
    #pragma unroll
    for (int c = 0; c < CC; c++) {
        float v = myacc[c * 32 + lane];
        #pragma unroll
        for (int o = 16; o > 0; o >>= 1) v += __shfl_xor_sync(0xffffffffu, v, o);
        if (lane == 0) atomicAdd(&g_sums[n][c][w], v);
        if (w == 0) {
            float cv = cacc[c * 32 + lane];
            #pragma unroll
            for (int o = 16; o > 0; o >>= 1) cv += __shfl_xor_sync(0xffffffffu, cv, o);
            if (lane == 0) atomicAdd(&g_counts[n][c], cv);
        }
    }
}

// ---------------------------------------------------------------------------
// Kernel 2: variance term. Thread-per-voxel; means in smem (x17 pad =>
// conflict-free gather); per-lane-column smem accumulator for var[label].
// ---------------------------------------------------------------------------
__global__ __launch_bounds__(512, 4)
void pass2_kernel(const float* __restrict__ x, const int* __restrict__ t) {
    __shared__ float means_s[CC * 17];                 // padded: bank (17c+e)%32 injective in c
    __shared__ float vacc[16 * CC * 32];               // 32 KB

    const int n    = blockIdx.y;
    const int tid  = threadIdx.x;
    const int w    = tid >> 5;
    const int lane = tid & 31;

    if (tid < CC * EE) {
        int c = tid >> 4, e = tid & 15;
        means_s[c * 17 + e] = g_sums[n][c][e] / g_counts[n][c];
    }
    for (int i = tid; i < 16 * CC * 32; i += 512) vacc[i] = 0.0f;
    __syncthreads();

    float* myv = vacc + w * (CC * 32);
    const float* xb = x + (size_t)n * EE * VV;
    const int*   tb = t + (size_t)n * VV;

    for (int v = blockIdx.x * 512 + tid; v < VV; v += gridDim.x * 512) {
        int lab = __ldcs(tb + v);
        const float* ms = means_s + lab * 17;
        float ss = 0.0f;
        #pragma unroll
        for (int e = 0; e < EE; e++) {
            float d = __ldcs(xb + (size_t)e * VV + v) - ms[e];
            ss = fmaf(d, d, ss);
        }
        float h = fmaxf(sqrtf(ss) - DELTA_VAR, 0.0f);
        myv[lab * 32 + lane] += h * h;
    }

    #pragma unroll
    for (int c = 0; c < CC; c++) {
        float v = myv[c * 32 + lane];
        #pragma unroll
        for (int o = 16; o > 0; o >>= 1) v += __shfl_xor_sync(0xffffffffu, v, o);
        if (lane == 0) atomicAdd(&g_var[n][c], v);
    }
}

// ---------------------------------------------------------------------------
// Kernel 3: finalize (tiny). One block of 512 threads.
// ---------------------------------------------------------------------------
__global__ void finalize_kernel(float* __restrict__ out) {
    __shared__ float means_s[NB][CC][EE];
    __shared__ float acc[NB][3];   // [n][0]=var, [1]=dist, [2]=reg

    const int tid = threadIdx.x;
    if (tid < NB * 3) (&acc[0][0])[tid] = 0.0f;
    if (tid < NB * CC * EE) {
        int n = tid >> 8, c = (tid >> 4) & 15, e = tid & 15;
        means_s[n][c][e] = g_sums[n][c][e] / g_counts[n][c];
    }
    __syncthreads();

    if (tid < NB * CC) {   // variance + regularizer terms
        int n = tid >> 4, c = tid & 15;
        atomicAdd(&acc[n][0], g_var[n][c] / g_counts[n][c]);
        float s = 0.0f;
        #pragma unroll
        for (int e = 0; e < EE; e++) {
            float m = means_s[n][c][e];
            s = fmaf(m, m, s);
        }
        atomicAdd(&acc[n][2], sqrtf(s));
    }

    // all-pairs hinged repulsion: tid encodes (n, a, b)
    {
        int n = tid >> 8, a = (tid >> 4) & 15, b = tid & 15;
        float s = 0.0f;
        #pragma unroll
        for (int e = 0; e < EE; e++) {
            float d = means_s[n][a][e] - means_s[n][b][e];
            s = fmaf(d, d, s);
        }
        float dmat = sqrtf(s);
        float rep  = (a == b) ? 0.0f : (2.0f * DELTA_DIST);
        float h    = fmaxf(rep - dmat, 0.0f);
        atomicAdd(&acc[n][1], h * h);
    }
    __syncthreads();

    if (tid == 0) {
        float loss = 0.0f;
        #pragma unroll
        for (int n = 0; n < NB; n++) {
            float var_term  = acc[n][0] / (float)CC;
            float dist_term = acc[n][1] / (float)(CC * (CC - 1));
            float reg_term  = acc[n][2] / (float)CC;
            loss += var_term + dist_term + 0.001f * reg_term;
        }
        out[0] = loss / (float)NB;
    }
}

// ---------------------------------------------------------------------------
extern "C" void kernel_launch(void* const* d_in, const int* in_sizes, int n_in,
                              void* d_out, int out_size) {
    const float* x = (const float*)d_in[0];   // [2,16,64,128,128] f32
    const int*   t = (const int*)d_in[1];     // [2,64,128,128]    i32
    float* out = (float*)d_out;

    init_kernel<<<1, 256>>>();
    pass1_kernel<<<dim3(P1_BLOCKS, NB), 512>>>(x, t);
    pass2_kernel<<<dim3(P2_BLOCKS, NB), 512>>>(x, t);
    finalize_kernel<<<1, 512>>>(out);
}

// round 5
// speedup vs baseline: 1.7883x; 1.7883x over previous
#include <cuda_runtime.h>
#include <cuda_bf16.h>
#include <math.h>

// Problem constants
#define NB 2
#define EE 16
#define CC 16
#define VV (64*128*128)              // 1,048,576 voxels per batch

#define CHUNK1 2048
#define P1_GX (VV / CHUNK1)          // 512 blocks in x
#define P2_THREADS 256
#define P2_GX (VV / (P2_THREADS*4))  // 1024 blocks in x (one float4 per thread)

#define DELTA_VAR 0.5f
#define DELTA_DIST 1.5f

// Scratch (device globals; zero-initialized at load; finalize re-zeros them
// after consuming, so every kernel_launch call sees zeros -> deterministic).
__device__ float g_sums[NB][CC][EE];
__device__ float g_counts[NB][CC];
__device__ float g_var[NB][CC];

// ---------------------------------------------------------------------------
// Pass 1: per-cluster sums + counts.
// Block = (chunk of 2048 voxels) x (all 16 embedding planes).
// 16 warps; warp w owns plane e=w. Labels staged once in smem (int4).
// Each lane owns private smem column acc[c*32+lane] -> bank==lane, no
// conflicts, no atomics in the hot loop. float4 loads for MLP.
// smem: 8KB labels + 32KB acc + 2KB cacc = 42KB (< 48KB static limit).
// ---------------------------------------------------------------------------
__global__ __launch_bounds__(512, 2)
void pass1_kernel(const float* __restrict__ x, const int* __restrict__ t) {
    __shared__ int   labels[CHUNK1];        // 8 KB
    __shared__ float acc[EE][CC * 32];      // 32 KB
    __shared__ float cacc[CC * 32];         // 2 KB (counts, warp 0)

    const int n    = blockIdx.y;
    const int base = blockIdx.x * CHUNK1;
    const int tid  = threadIdx.x;
    const int w    = tid >> 5;
    const int lane = tid & 31;

    const int4* tp = (const int4*)(t + (size_t)n * VV + base);
    for (int i = tid; i < CHUNK1 / 4; i += 512) ((int4*)labels)[i] = tp[i];
    for (int i = tid; i < EE * CC * 32; i += 512) (&acc[0][0])[i] = 0.0f;
    for (int i = tid; i < CC * 32;      i += 512) cacc[i] = 0.0f;
    __syncthreads();

    float* myacc = acc[w];
    const float* xp = x + ((size_t)n * EE + w) * VV + base;

    if (w == 0) {
        #pragma unroll 4
        for (int i = lane * 4; i < CHUNK1; i += 128) {
            float4 v = *(const float4*)(xp + i);
            int4  lb = *(const int4*)(labels + i);
            myacc[lb.x * 32 + lane] += v.x;  cacc[lb.x * 32 + lane] += 1.0f;
            myacc[lb.y * 32 + lane] += v.y;  cacc[lb.y * 32 + lane] += 1.0f;
            myacc[lb.z * 32 + lane] += v.z;  cacc[lb.z * 32 + lane] += 1.0f;
            myacc[lb.w * 32 + lane] += v.w;  cacc[lb.w * 32 + lane] += 1.0f;
        }
    } else {
        #pragma unroll 4
        for (int i = lane * 4; i < CHUNK1; i += 128) {
            float4 v = *(const float4*)(xp + i);
            int4  lb = *(const int4*)(labels + i);
            myacc[lb.x * 32 + lane] += v.x;
            myacc[lb.y * 32 + lane] += v.y;
            myacc[lb.z * 32 + lane] += v.z;
            myacc[lb.w * 32 + lane] += v.w;
        }
    }
    __syncwarp();

    #pragma unroll
    for (int c = 0; c < CC; c++) {
        float v = myacc[c * 32 + lane];
        #pragma unroll
        for (int o = 16; o > 0; o >>= 1) v += __shfl_xor_sync(0xffffffffu, v, o);
        if (lane == 0) atomicAdd(&g_sums[n][c][w], v);
        if (w == 0) {
            float cv = cacc[c * 32 + lane];
            #pragma unroll
            for (int o = 16; o > 0; o >>= 1) cv += __shfl_xor_sync(0xffffffffu, cv, o);
            if (lane == 0) atomicAdd(&g_counts[n][c], cv);
        }
    }
}

// ---------------------------------------------------------------------------
// Pass 2: variance term. One float4 (4 voxels) per thread, one shot.
// 8 independent LDG.128 in flight per batch of planes (MLP=8).
// Means in smem, stride 20 floats (<=2-way conflict for random labels).
// Traversal REVERSED vs pass 1 so the tail of x (freshest in L2) is hit first.
// ---------------------------------------------------------------------------
__global__ __launch_bounds__(P2_THREADS, 4)
void pass2_kernel(const float* __restrict__ x, const int* __restrict__ t) {
    __shared__ float means_s[CC * 20];      // padded stride 20
    __shared__ float vacc[8][CC * 32];      // 16 KB (8 warps)
    __shared__ float wpart[8][CC];

    const int n    = blockIdx.y;
    const int tid  = threadIdx.x;
    const int w    = tid >> 5;
    const int lane = tid & 31;

    if (tid < CC * EE) {
        int c = tid >> 4, e = tid & 15;
        means_s[c * 20 + e] = g_sums[n][c][e] / g_counts[n][c];
    }
    for (int i = tid; i < 8 * CC * 32; i += P2_THREADS) (&vacc[0][0])[i] = 0.0f;
    __syncthreads();

    // reversed bijective index -> 4 consecutive voxels, warp stays contiguous
    const int idx = (P2_GX * P2_THREADS - 1) - (blockIdx.x * P2_THREADS + tid);
    const int v   = idx * 4;

    const float* xb = x + (size_t)n * EE * VV;
    const int4 lb = *(const int4*)(t + (size_t)n * VV + v);

    float ss0 = 0.0f, ss1 = 0.0f, ss2 = 0.0f, ss3 = 0.0f;
    #pragma unroll
    for (int eo = 0; eo < EE; eo += 8) {
        float4 xv[8];
        #pragma unroll
        for (int e = 0; e < 8; e++)
            xv[e] = *(const float4*)(xb + (size_t)(eo + e) * VV + v);
        #pragma unroll
        for (int e = 0; e < 8; e++) {
            const int ee = eo + e;
            float d;
            d = xv[e].x - means_s[lb.x * 20 + ee]; ss0 = fmaf(d, d, ss0);
            d = xv[e].y - means_s[lb.y * 20 + ee]; ss1 = fmaf(d, d, ss1);
            d = xv[e].z - means_s[lb.z * 20 + ee]; ss2 = fmaf(d, d, ss2);
            d = xv[e].w - means_s[lb.w * 20 + ee]; ss3 = fmaf(d, d, ss3);
        }
    }

    float* myv = vacc[w];
    float h;
    h = fmaxf(sqrtf(ss0) - DELTA_VAR, 0.0f); myv[lb.x * 32 + lane] += h * h;
    h = fmaxf(sqrtf(ss1) - DELTA_VAR, 0.0f); myv[lb.y * 32 + lane] += h * h;
    h = fmaxf(sqrtf(ss2) - DELTA_VAR, 0.0f); myv[lb.z * 32 + lane] += h * h;
    h = fmaxf(sqrtf(ss3) - DELTA_VAR, 0.0f); myv[lb.w * 32 + lane] += h * h;
    __syncwarp();

    #pragma unroll
    for (int c = 0; c < CC; c++) {
        float vv = myv[c * 32 + lane];
        #pragma unroll
        for (int o = 16; o > 0; o >>= 1) vv += __shfl_xor_sync(0xffffffffu, vv, o);
        if (lane == 0) wpart[w][c] = vv;
    }
    __syncthreads();

    if (tid < CC) {
        float s = 0.0f;
        #pragma unroll
        for (int ww = 0; ww < 8; ww++) s += wpart[ww][tid];
        atomicAdd(&g_var[n][tid], s);
    }
}

// ---------------------------------------------------------------------------
// Finalize: tiny. Computes loss, then RE-ZEROS the scratch globals so the
// next call (graph replay) starts clean without a separate init kernel.
// ---------------------------------------------------------------------------
__global__ void finalize_kernel(float* __restrict__ out) {
    __shared__ float means_s[NB][CC][EE];
    __shared__ float acc[NB][3];   // [n][0]=var, [1]=dist, [2]=reg

    const int tid = threadIdx.x;
    if (tid < NB * 3) (&acc[0][0])[tid] = 0.0f;
    if (tid < NB * CC * EE) {
        int n = tid >> 8, c = (tid >> 4) & 15, e = tid & 15;
        means_s[n][c][e] = g_sums[n][c][e] / g_counts[n][c];
    }
    __syncthreads();

    if (tid < NB * CC) {   // variance + regularizer terms
        int n = tid >> 4, c = tid & 15;
        atomicAdd(&acc[n][0], g_var[n][c] / g_counts[n][c]);
        float s = 0.0f;
        #pragma unroll
        for (int e = 0; e < EE; e++) {
            float m = means_s[n][c][e];
            s = fmaf(m, m, s);
        }
        atomicAdd(&acc[n][2], sqrtf(s));
    }

    {   // all-pairs hinged repulsion: tid encodes (n, a, b)
        int n = tid >> 8, a = (tid >> 4) & 15, b = tid & 15;
        float s = 0.0f;
        #pragma unroll
        for (int e = 0; e < EE; e++) {
            float d = means_s[n][a][e] - means_s[n][b][e];
            s = fmaf(d, d, s);
        }
        float dmat = sqrtf(s);
        float rep  = (a == b) ? 0.0f : (2.0f * DELTA_DIST);
        float h    = fmaxf(rep - dmat, 0.0f);
        atomicAdd(&acc[n][1], h * h);
    }
    __syncthreads();

    if (tid == 0) {
        float loss = 0.0f;
        #pragma unroll
        for (int n = 0; n < NB; n++) {
            float var_term  = acc[n][0] / (float)CC;
            float dist_term = acc[n][1] / (float)(CC * (CC - 1));
            float reg_term  = acc[n][2] / (float)CC;
            loss += var_term + dist_term + 0.001f * reg_term;
        }
        out[0] = loss / (float)NB;
    }
    __syncthreads();

    // re-zero scratch for the next invocation (all reads above are done)
    {
        float* s = &g_sums[0][0][0];
        for (int i = tid; i < NB * CC * EE; i += blockDim.x) s[i] = 0.0f;
        float* c = &g_counts[0][0];
        for (int i = tid; i < NB * CC; i += blockDim.x) c[i] = 0.0f;
        float* vv = &g_var[0][0];
        for (int i = tid; i < NB * CC; i += blockDim.x) vv[i] = 0.0f;
    }
}

// ---------------------------------------------------------------------------
extern "C" void kernel_launch(void* const* d_in, const int* in_sizes, int n_in,
                              void* d_out, int out_size) {
    const float* x = (const float*)d_in[0];   // [2,16,64,128,128] f32
    const int*   t = (const int*)d_in[1];     // [2,64,128,128]    i32
    float* out = (float*)d_out;

    pass1_kernel<<<dim3(P1_GX, NB), 512>>>(x, t);
    pass2_kernel<<<dim3(P2_GX, NB), P2_THREADS>>>(x, t);
    finalize_kernel<<<1, 512>>>(out);
}